// round 5
// baseline (speedup 1.0000x reference)
#include <cuda_runtime.h>
#include <cuda_bf16.h>
#include <math.h>

#define B_   2
#define T_   1024
#define D_   768
#define H_   12
#define L_   4
#define E_   8
#define DFF_ 3072
#define V_   32000
#define HEAD_ 64
#define BT_  (B_ * T_)      // 2048
#define TD3_ (3 * D_)       // 2304

// ---------------- scratch (device globals; no allocation) ----------------
__device__ float g_x  [BT_ * D_];
__device__ float g_h  [BT_ * D_];
__device__ float g_qkv[BT_ * TD3_];
__device__ float g_sc [(size_t)B_ * H_ * T_ * T_];
__device__ float g_ao [BT_ * D_];
__device__ float g_w  [BT_ * E_];
__device__ float g_hid[BT_ * DFF_];
__device__ float g_ahi[BT_ * D_];
__device__ float g_alo[BT_ * D_];
__device__ float g_bhi[(size_t)V_ * D_];
__device__ float g_blo[(size_t)V_ * D_];
__device__ float g_chi[BT_ * DFF_];
__device__ float g_clo[BT_ * DFF_];

__device__ __forceinline__ float tf32_rn(float x) {
    unsigned u;
    asm("cvt.rna.tf32.f32 %0, %1;" : "=r"(u) : "f"(x));
    return __uint_as_float(u);
}

// ---------------- embedding ----------------
__global__ void embed_kernel(const int* __restrict__ tokens,
                             const float* __restrict__ wte,
                             const float* __restrict__ wpe,
                             float* __restrict__ x) {
    int r = blockIdx.x;
    int t = r & (T_ - 1);
    int tok = tokens[r];
    const float* we = wte + (size_t)tok * D_;
    const float* pe = wpe + (size_t)t * D_;
    float* xr = x + (size_t)r * D_;
    for (int i = threadIdx.x; i < D_; i += 256) xr[i] = we[i] + pe[i];
}

// ---------------- layernorm ----------------
__global__ void ln_kernel(const float* __restrict__ in,
                          const float* __restrict__ g,
                          const float* __restrict__ b,
                          float* __restrict__ out) {
    int r = blockIdx.x, tid = threadIdx.x;
    const float* xr = in + (size_t)r * D_;
    float v[3], s = 0.f, ss = 0.f;
#pragma unroll
    for (int n = 0; n < 3; n++) {
        float t = xr[tid + n * 256];
        v[n] = t; s += t; ss += t * t;
    }
    __shared__ float r1[256], r2[256];
    r1[tid] = s; r2[tid] = ss;
    __syncthreads();
    for (int o = 128; o > 0; o >>= 1) {
        if (tid < o) { r1[tid] += r1[tid + o]; r2[tid] += r2[tid + o]; }
        __syncthreads();
    }
    float mu = r1[0] * (1.f / D_);
    float var = r2[0] * (1.f / D_) - mu * mu;
    float rstd = rsqrtf(var + 1e-5f);
    float* orow = out + (size_t)r * D_;
#pragma unroll
    for (int n = 0; n < 3; n++) {
        int i = tid + n * 256;
        orow[i] = (v[n] - mu) * rstd * g[i] + b[i];
    }
}

// ---------------- split fp32 -> (hi, lo) tf32-rounded fp32, flat layout ----------------
__global__ void split2_kernel(const float* __restrict__ in,
                              float* __restrict__ hi, float* __restrict__ lo,
                              int n) {
    int idx = blockIdx.x * 256 + threadIdx.x;
    if (idx >= n) return;
    float a = in[idx];
    float h = tf32_rn(a);
    hi[idx] = h;
    lo[idx] = tf32_rn(a - h);
}

// ---------------- tf32 tensor-core NT GEMM ----------------
// C[M,N] = A[M,K] * B[N,K]^T   (A,B fp32 pre-rounded to tf32 bits)
// MODE 0: C = acc   1: C = max(C+acc, 0)   2: C += acc   3: C += rs[m*stride]*acc
#define BK 16
#define PADF 4

__device__ __forceinline__ unsigned su32(const void* p) {
    return (unsigned)__cvta_generic_to_shared(p);
}
__device__ __forceinline__ void cp16(void* s, const void* g) {
    asm volatile("cp.async.cg.shared.global [%0], [%1], 16;\n" :: "r"(su32(s)), "l"(g));
}
#define CP_COMMIT() asm volatile("cp.async.commit_group;\n" ::: "memory")
#define CP_WAIT1()  asm volatile("cp.async.wait_group 1;\n" ::: "memory")
#define LDSM4(r0,r1,r2,r3,addr) \
    asm volatile("ldmatrix.sync.aligned.m8n8.x4.shared.b16 {%0,%1,%2,%3}, [%4];" \
                 : "=r"(r0),"=r"(r1),"=r"(r2),"=r"(r3) : "r"(addr))
#define MMA1688(c,a,b0,b1) \
    asm volatile("mma.sync.aligned.m16n8k8.row.col.f32.tf32.tf32.f32 " \
                 "{%0,%1,%2,%3},{%4,%5,%6,%7},{%8,%9},{%0,%1,%2,%3};" \
                 : "+f"(c[0]),"+f"(c[1]),"+f"(c[2]),"+f"(c[3]) \
                 : "r"(a[0]),"r"(a[1]),"r"(a[2]),"r"(a[3]),"r"(b0),"r"(b1))

template <int MODE, int BNT>
__global__ void __launch_bounds__(256) gemm_tf32(
    const float* __restrict__ A, const float* __restrict__ B,
    float* __restrict__ C, int M, int N, int K,
    const float* __restrict__ rs, int rs_stride) {
    constexpr int WN  = BNT / 4;        // per-warp n extent: 32 or 16
    constexpr int NJ  = WN / 8;         // 4 or 2
    constexpr int NG2 = WN / 16;        // 2 or 1
    __shared__ __align__(16) float As[2][128][BK + PADF];
    __shared__ __align__(16) float Bs[2][BNT][BK + PADF];
    const int tid = threadIdx.x;
    const int lane = tid & 31, warp = tid >> 5;
    const int wm = (warp >> 2) * 64;    // 0 or 64
    const int wn = (warp & 3) * WN;
    const int m0 = blockIdx.x * 128, n0 = blockIdx.y * BNT;

    const int ar = tid >> 1, ac = (tid & 1) * 8;
    const float* ga = A + (size_t)(m0 + ar) * K + ac;
    int br, bc;
    if (BNT == 128) { br = tid >> 1; bc = (tid & 1) * 8; }
    else            { br = tid >> 2; bc = (tid & 3) * 4; }
    const float* gb = B + (size_t)(n0 + br) * K + bc;

    float c[4][NJ][4];
#pragma unroll
    for (int i = 0; i < 4; i++)
#pragma unroll
        for (int j = 0; j < NJ; j++)
#pragma unroll
            for (int q = 0; q < 4; q++) c[i][j][q] = 0.f;

    // prologue: tile 0
    cp16(&As[0][ar][ac],     ga);
    cp16(&As[0][ar][ac + 4], ga + 4);
    if (BNT == 128) {
        cp16(&Bs[0][br][bc],     gb);
        cp16(&Bs[0][br][bc + 4], gb + 4);
    } else {
        cp16(&Bs[0][br][bc], gb);
    }
    CP_COMMIT();

    const int ktiles = K / BK;
    for (int kt = 0; kt < ktiles; kt++) {
        if (kt + 1 < ktiles) {
            int buf = (kt + 1) & 1, k0 = (kt + 1) * BK;
            cp16(&As[buf][ar][ac],     ga + k0);
            cp16(&As[buf][ar][ac + 4], ga + k0 + 4);
            if (BNT == 128) {
                cp16(&Bs[buf][br][bc],     gb + k0);
                cp16(&Bs[buf][br][bc + 4], gb + k0 + 4);
            } else {
                cp16(&Bs[buf][br][bc], gb + k0);
            }
        }
        CP_COMMIT();
        CP_WAIT1();
        __syncthreads();
        const int buf = kt & 1;
#pragma unroll
        for (int kh = 0; kh < 2; kh++) {
            const int kbase = kh * 8;
            unsigned a[4][4], bb[NG2][4];
            const int arow = wm + (lane & 15);
            const int acol = kbase + ((lane >> 4) << 2);
#pragma unroll
            for (int mi = 0; mi < 4; mi++) {
                unsigned ad = su32(&As[buf][arow + mi * 16][acol]);
                LDSM4(a[mi][0], a[mi][1], a[mi][2], a[mi][3], ad);
            }
            const int brow = wn + ((lane & 16) >> 1) + (lane & 7);
            const int bcol = kbase + ((lane & 8) >> 1);
#pragma unroll
            for (int g2 = 0; g2 < NG2; g2++) {
                unsigned ad = su32(&Bs[buf][brow + g2 * 16][bcol]);
                LDSM4(bb[g2][0], bb[g2][1], bb[g2][2], bb[g2][3], ad);
            }
#pragma unroll
            for (int mi = 0; mi < 4; mi++)
#pragma unroll
                for (int nj = 0; nj < NJ; nj++) {
                    unsigned b0 = bb[nj >> 1][(nj & 1) * 2];
                    unsigned b1 = bb[nj >> 1][(nj & 1) * 2 + 1];
                    MMA1688(c[mi][nj], a[mi], b0, b1);
                }
        }
        __syncthreads();
    }

    // epilogue
    const int crow = lane >> 2, ccol = (lane & 3) * 2;
#pragma unroll
    for (int mi = 0; mi < 4; mi++) {
#pragma unroll
        for (int half = 0; half < 2; half++) {
            const int m = m0 + wm + mi * 16 + crow + half * 8;
            float s = (MODE == 3) ? rs[(size_t)m * rs_stride] : 0.f;
#pragma unroll
            for (int nj = 0; nj < NJ; nj++) {
                const int n = n0 + wn + nj * 8 + ccol;
                float v0 = c[mi][nj][half * 2 + 0];
                float v1 = c[mi][nj][half * 2 + 1];
                float* p = C + (size_t)m * N + n;
                if (MODE == 0)      { p[0] = v0;                      p[1] = v1; }
                else if (MODE == 1) { p[0] = fmaxf(p[0] + v0, 0.f);   p[1] = fmaxf(p[1] + v1, 0.f); }
                else if (MODE == 2) { p[0] += v0;                     p[1] += v1; }
                else                { p[0] += s * v0;                 p[1] += s * v1; }
            }
        }
    }
}

// ---------------- attention: S = Q K^T * scale (causal tiles only) ----------------
__global__ void __launch_bounds__(256) attn_scores(const float* __restrict__ qkv,
                                                   float* __restrict__ sc) {
    int kt = blockIdx.x, qt = blockIdx.y, bh = blockIdx.z;
    if (kt > qt) return;
    int b = bh / H_, h = bh - b * H_;
    const float* Qb = qkv + (size_t)b * T_ * TD3_ + h * HEAD_;
    const float* Kb = Qb + D_;
    __shared__ float As[16][65], Bs[16][65];
    int tid = threadIdx.x;
    int m = tid >> 2, k4 = (tid & 3) * 4;
    int ty = tid >> 4, tx = tid & 15;
    float acc[4][4] = {};
    for (int k0 = 0; k0 < HEAD_; k0 += 16) {
        float4 a   = *(const float4*)(Qb + (size_t)(qt * 64 + m) * TD3_ + k0 + k4);
        float4 bbv = *(const float4*)(Kb + (size_t)(kt * 64 + m) * TD3_ + k0 + k4);
        __syncthreads();
        As[k4 + 0][m] = a.x;   As[k4 + 1][m] = a.y;   As[k4 + 2][m] = a.z;   As[k4 + 3][m] = a.w;
        Bs[k4 + 0][m] = bbv.x; Bs[k4 + 1][m] = bbv.y; Bs[k4 + 2][m] = bbv.z; Bs[k4 + 3][m] = bbv.w;
        __syncthreads();
#pragma unroll
        for (int k = 0; k < 16; k++) {
            float av[4], bv[4];
#pragma unroll
            for (int i = 0; i < 4; i++) av[i] = As[k][ty * 4 + i];
#pragma unroll
            for (int j = 0; j < 4; j++) bv[j] = Bs[k][tx * 4 + j];
#pragma unroll
            for (int i = 0; i < 4; i++)
#pragma unroll
                for (int j = 0; j < 4; j++) acc[i][j] += av[i] * bv[j];
        }
    }
    float* out = sc + ((size_t)bh << 20);
#pragma unroll
    for (int i = 0; i < 4; i++) {
        int q = qt * 64 + ty * 4 + i;
#pragma unroll
        for (int j = 0; j < 4; j++) {
            int kk = kt * 64 + tx * 4 + j;
            float v = acc[i][j] * 0.125f;
            if (kk > q) v = -1e30f;
            out[(size_t)q * T_ + kk] = v;
        }
    }
}

// ---------------- row softmax over [0, kend) ----------------
__global__ void softmax_rows(float* __restrict__ sc) {
    int q = blockIdx.x, bh = blockIdx.y, tid = threadIdx.x;
    float* row = sc + ((size_t)bh << 20) + (size_t)q * T_;
    int kend = ((q >> 6) + 1) << 6;
    float lmax = -3e38f;
    for (int i = tid; i < kend; i += 256) lmax = fmaxf(lmax, row[i]);
    __shared__ float red[256];
    red[tid] = lmax; __syncthreads();
    for (int o = 128; o > 0; o >>= 1) {
        if (tid < o) red[tid] = fmaxf(red[tid], red[tid + o]);
        __syncthreads();
    }
    float m = red[0];
    __syncthreads();
    float v[4]; int n = 0; float lsum = 0.f;
    for (int i = tid; i < kend; i += 256) {
        float e = __expf(row[i] - m);
        v[n++] = e; lsum += e;
    }
    red[tid] = lsum; __syncthreads();
    for (int o = 128; o > 0; o >>= 1) {
        if (tid < o) red[tid] += red[tid + o];
        __syncthreads();
    }
    float inv = 1.f / red[0];
    n = 0;
    for (int i = tid; i < kend; i += 256) row[i] = v[n++] * inv;
}

// ---------------- attention: O = P V ----------------
__global__ void __launch_bounds__(256) attn_out(const float* __restrict__ sc,
                                                const float* __restrict__ qkv,
                                                float* __restrict__ ao) {
    int qt = blockIdx.x, bh = blockIdx.y;
    int b = bh / H_, h = bh - b * H_;
    const float* P = sc + ((size_t)bh << 20) + (size_t)qt * 64 * T_;
    const float* V = qkv + (size_t)b * T_ * TD3_ + 2 * D_ + h * HEAD_;
    __shared__ float Ps[64][20];
    __shared__ float Vs[16][64];
    int tid = threadIdx.x;
    int m = tid >> 2, k4 = (tid & 3) * 4;
    int kv = tid >> 4, j4 = (tid & 15) * 4;
    int ty = tid >> 4, tx = tid & 15;
    float acc[4][4] = {};
    int kmax = (qt + 1) * 64;
    for (int k0 = 0; k0 < kmax; k0 += 16) {
        float4 p  = *(const float4*)(P + (size_t)m * T_ + k0 + k4);
        float4 vv = *(const float4*)(V + (size_t)(k0 + kv) * TD3_ + j4);
        __syncthreads();
        *(float4*)&Ps[m][k4] = p;
        *(float4*)&Vs[kv][j4] = vv;
        __syncthreads();
#pragma unroll
        for (int k = 0; k < 16; k++) {
            float pv[4], vb[4];
#pragma unroll
            for (int i = 0; i < 4; i++) pv[i] = Ps[ty * 4 + i][k];
            *(float4*)vb = *(const float4*)&Vs[k][tx * 4];
#pragma unroll
            for (int i = 0; i < 4; i++)
#pragma unroll
                for (int j = 0; j < 4; j++) acc[i][j] += pv[i] * vb[j];
        }
    }
    float* O = ao + (size_t)(b * T_ + qt * 64) * D_ + h * HEAD_;
#pragma unroll
    for (int i = 0; i < 4; i++)
#pragma unroll
        for (int j = 0; j < 4; j++)
            O[(size_t)(ty * 4 + i) * D_ + tx * 4 + j] = acc[i][j];
}

// ---------------- router ----------------
__global__ void router_kernel(const float* __restrict__ h,
                              const float* __restrict__ rw,
                              float* __restrict__ w) {
    int r = blockIdx.x;
    int warp = threadIdx.x >> 5, lane = threadIdx.x & 31;
    const float* hr = h + (size_t)r * D_;
    const float* we = rw + (size_t)warp * D_;
    float dot = 0.f;
    for (int i = lane; i < D_; i += 32) dot += hr[i] * we[i];
    for (int o = 16; o > 0; o >>= 1) dot += __shfl_xor_sync(0xffffffffu, dot, o);
    __shared__ float s[E_];
    if (lane == 0) s[warp] = dot;
    __syncthreads();
    if (threadIdx.x == 0) {
        float mx = s[0];
        for (int e = 1; e < E_; e++) mx = fmaxf(mx, s[e]);
        float p[E_], sum = 0.f;
        for (int e = 0; e < E_; e++) { p[e] = __expf(s[e] - mx); sum += p[e]; }
        float inv = 1.f / sum;
        for (int e = 0; e < E_; e++) p[e] *= inv;
        int i1 = 0;
        for (int e = 1; e < E_; e++) if (s[e] > s[i1]) i1 = e;
        int i2 = (i1 == 0) ? 1 : 0;
        for (int e = 0; e < E_; e++) if (e != i1 && s[e] > s[i2]) i2 = e;
        float denom = p[i1] + p[i2] + 1e-8f;
        for (int e = 0; e < E_; e++)
            w[(size_t)r * E_ + e] = (e == i1 || e == i2) ? p[e] / denom : 0.f;
    }
}

// ---------------- host helpers ----------------
static inline void split2(const float* in, float* hi, float* lo, size_t n) {
    split2_kernel<<<(unsigned)((n + 255) / 256), 256>>>(in, hi, lo, (int)n);
}

extern "C" void kernel_launch(void* const* d_in, const int* in_sizes, int n_in,
                              void* d_out, int out_size) {
    (void)in_sizes; (void)n_in; (void)out_size;
    const int*   tokens   = (const int*)  d_in[0];
    const float* wte      = (const float*)d_in[1];
    const float* wpe      = (const float*)d_in[2];
    const float* norm0_g  = (const float*)d_in[3];
    const float* norm0_b  = (const float*)d_in[4];
    const float* norm1_g  = (const float*)d_in[5];
    const float* norm1_b  = (const float*)d_in[6];
    const float* norm2_g  = (const float*)d_in[7];
    const float* norm2_b  = (const float*)d_in[8];
    const float* qkv_w    = (const float*)d_in[9];
    const float* proj_w   = (const float*)d_in[10];
    const float* router_w = (const float*)d_in[11];
    const float* fc1      = (const float*)d_in[12];
    const float* fc2      = (const float*)d_in[13];
    const float* lm_head  = (const float*)d_in[14];
    float* out = (float*)d_out;

    float *x, *h, *qkv, *sc, *ao, *w, *hid, *ahi, *alo, *bhi, *blo, *chi, *clo;
    cudaGetSymbolAddress((void**)&x,   g_x);
    cudaGetSymbolAddress((void**)&h,   g_h);
    cudaGetSymbolAddress((void**)&qkv, g_qkv);
    cudaGetSymbolAddress((void**)&sc,  g_sc);
    cudaGetSymbolAddress((void**)&ao,  g_ao);
    cudaGetSymbolAddress((void**)&w,   g_w);
    cudaGetSymbolAddress((void**)&hid, g_hid);
    cudaGetSymbolAddress((void**)&ahi, g_ahi);
    cudaGetSymbolAddress((void**)&alo, g_alo);
    cudaGetSymbolAddress((void**)&bhi, g_bhi);
    cudaGetSymbolAddress((void**)&blo, g_blo);
    cudaGetSymbolAddress((void**)&chi, g_chi);
    cudaGetSymbolAddress((void**)&clo, g_clo);

    embed_kernel<<<BT_, 256>>>(tokens, wte, wpe, x);
    ln_kernel<<<BT_, 256>>>(x, norm0_g, norm0_b, x);

    for (int l = 0; l < L_; l++) {
        // --- attention ---
        ln_kernel<<<BT_, 256>>>(x, norm1_g + l * D_, norm1_b + l * D_, h);
        split2(h, ahi, alo, (size_t)BT_ * D_);
        split2(qkv_w + (size_t)l * TD3_ * D_, bhi, blo, (size_t)TD3_ * D_);
        {
            dim3 g(BT_ / 128, TD3_ / 128);
            gemm_tf32<0, 128><<<g, 256>>>(ahi, bhi, qkv, BT_, TD3_, D_, nullptr, 0);
            gemm_tf32<2, 128><<<g, 256>>>(alo, bhi, qkv, BT_, TD3_, D_, nullptr, 0);
            gemm_tf32<2, 128><<<g, 256>>>(ahi, blo, qkv, BT_, TD3_, D_, nullptr, 0);
        }
        {
            dim3 g(T_ / 64, T_ / 64, B_ * H_);
            attn_scores<<<g, 256>>>(qkv, sc);
        }
        {
            dim3 g(T_, B_ * H_);
            softmax_rows<<<g, 256>>>(sc);
        }
        {
            dim3 g(T_ / 64, B_ * H_);
            attn_out<<<g, 256>>>(sc, qkv, ao);
        }
        split2(ao, ahi, alo, (size_t)BT_ * D_);
        split2(proj_w + (size_t)l * D_ * D_, bhi, blo, (size_t)D_ * D_);
        {
            dim3 g(BT_ / 128, D_ / 64);
            gemm_tf32<2, 64><<<g, 256>>>(ahi, bhi, x, BT_, D_, D_, nullptr, 0);
            gemm_tf32<2, 64><<<g, 256>>>(alo, bhi, x, BT_, D_, D_, nullptr, 0);
            gemm_tf32<2, 64><<<g, 256>>>(ahi, blo, x, BT_, D_, D_, nullptr, 0);
        }
        // --- MoE ---
        ln_kernel<<<BT_, 256>>>(x, norm2_g + l * D_, norm2_b + l * D_, h);
        router_kernel<<<BT_, 256>>>(h, router_w + (size_t)l * E_ * D_, w);
        split2(h, ahi, alo, (size_t)BT_ * D_);
        for (int e = 0; e < E_; e++) {
            split2(fc1 + ((size_t)(l * E_ + e)) * DFF_ * D_, bhi, blo, (size_t)DFF_ * D_);
            {
                dim3 g(BT_ / 128, DFF_ / 128);
                gemm_tf32<0, 128><<<g, 256>>>(ahi, bhi, hid, BT_, DFF_, D_, nullptr, 0);
                gemm_tf32<2, 128><<<g, 256>>>(alo, bhi, hid, BT_, DFF_, D_, nullptr, 0);
                gemm_tf32<1, 128><<<g, 256>>>(ahi, blo, hid, BT_, DFF_, D_, nullptr, 0); // relu last
            }
            split2(hid, chi, clo, (size_t)BT_ * DFF_);
            split2(fc2 + ((size_t)(l * E_ + e)) * D_ * DFF_, bhi, blo, (size_t)D_ * DFF_);
            {
                dim3 g(BT_ / 128, D_ / 64);
                gemm_tf32<3, 64><<<g, 256>>>(chi, bhi, x, BT_, D_, DFF_, w + e, E_);
                gemm_tf32<3, 64><<<g, 256>>>(clo, bhi, x, BT_, D_, DFF_, w + e, E_);
                gemm_tf32<3, 64><<<g, 256>>>(chi, blo, x, BT_, D_, DFF_, w + e, E_);
            }
        }
    }
    split2(x, ahi, alo, (size_t)BT_ * D_);
    split2(lm_head, bhi, blo, (size_t)V_ * D_);
    {
        dim3 g(BT_ / 128, V_ / 128);
        gemm_tf32<0, 128><<<g, 256>>>(ahi, bhi, out, BT_, V_, D_, nullptr, 0);
        gemm_tf32<2, 128><<<g, 256>>>(alo, bhi, out, BT_, V_, D_, nullptr, 0);
        gemm_tf32<2, 128><<<g, 256>>>(ahi, blo, out, BT_, V_, D_, nullptr, 0);
    }
}

// round 13
// speedup vs baseline: 2.0869x; 2.0869x over previous
#include <cuda_runtime.h>
#include <cuda_fp16.h>
#include <math.h>
#include <stdint.h>

#define B_   2
#define T_   1024
#define D_   768
#define H_   12
#define L_   4
#define E_   8
#define DFF_ 3072
#define V_   32000
#define HEAD_ 64
#define BT_  (B_ * T_)      // 2048
#define TD3_ (3 * D_)       // 2304

// ---------------- scratch (device globals; no allocation) ----------------
__device__ float g_x  [BT_ * D_];
__device__ float g_h  [BT_ * D_];
__device__ float g_qkv[BT_ * TD3_];
__device__ float g_sc [(size_t)B_ * H_ * T_ * T_];
__device__ float g_ao [BT_ * D_];
__device__ float g_w  [BT_ * E_];
__device__ float g_hid[BT_ * DFF_];
__device__ __half g_ahi[BT_ * D_];
__device__ __half g_alo[BT_ * D_];
__device__ __half g_bhi[(size_t)V_ * D_];
__device__ __half g_blo[(size_t)V_ * D_];
__device__ __half g_chi[BT_ * DFF_];
__device__ __half g_clo[BT_ * DFF_];

__device__ __forceinline__ unsigned su32(const void* p) {
    return (unsigned)__cvta_generic_to_shared(p);
}
__device__ __forceinline__ void cp16(void* s, const void* g) {
    asm volatile("cp.async.cg.shared.global [%0], [%1], 16;\n" :: "r"(su32(s)), "l"(g));
}
#define CP_COMMIT() asm volatile("cp.async.commit_group;\n" ::: "memory")
#define CP_WAIT1()  asm volatile("cp.async.wait_group 1;\n" ::: "memory")
#define LDSM4(r0,r1,r2,r3,addr) \
    asm volatile("ldmatrix.sync.aligned.m8n8.x4.shared.b16 {%0,%1,%2,%3}, [%4];" \
                 : "=r"(r0),"=r"(r1),"=r"(r2),"=r"(r3) : "r"(addr))
#define MMA16816F(c,a,b0,b1) \
    asm volatile("mma.sync.aligned.m16n8k16.row.col.f32.f16.f16.f32 " \
                 "{%0,%1,%2,%3},{%4,%5,%6,%7},{%8,%9},{%0,%1,%2,%3};" \
                 : "+f"(c[0]),"+f"(c[1]),"+f"(c[2]),"+f"(c[3]) \
                 : "r"(a[0]),"r"(a[1]),"r"(a[2]),"r"(a[3]),"r"(b0),"r"(b1))

// ---------------- fp16 HMMA NT GEMM (one term per launch) ----------------
// C[M,N] = A[M,K] * B[N,K]^T   (A,B fp16 split halves; fp32 accumulate)
// MODE 0: C = acc   1: C = max(C+acc, 0)   2: C += acc   3: C += rs[m*stride]*acc
#define BKH 32
#define PADH 8

template <int MODE, int BNT>
__global__ void __launch_bounds__(256) gemm_f16(
    const __half* __restrict__ A, const __half* __restrict__ B,
    float* __restrict__ C, int M, int N, int K,
    const float* __restrict__ rs, int rs_stride) {
    constexpr int WN  = BNT / 4;        // 32 or 16
    constexpr int NJ  = WN / 8;         // 4 or 2
    constexpr int NG2 = WN / 16;        // 2 or 1
    __shared__ __align__(16) __half As[2][128][BKH + PADH];
    __shared__ __align__(16) __half Bs[2][BNT][BKH + PADH];
    const int tid = threadIdx.x;
    const int lane = tid & 31, warp = tid >> 5;
    const int wm = (warp >> 2) * 64;
    const int wn = (warp & 3) * WN;
    const int m0 = blockIdx.x * 128, n0 = blockIdx.y * BNT;

    // gmem load mapping: row = tid>>2 (0..63), 4 chunks of 8 halves (16B)
    const int lr = tid >> 2, lc = (tid & 3) * 8;
    const __half* ga = A + (size_t)(m0 + lr) * K + lc;
    const __half* gb = B + (size_t)(n0 + lr) * K + lc;

    float c[4][NJ][4];
#pragma unroll
    for (int i = 0; i < 4; i++)
#pragma unroll
        for (int j = 0; j < NJ; j++)
#pragma unroll
            for (int q = 0; q < 4; q++) c[i][j][q] = 0.f;

    // prologue: tile 0
    cp16(&As[0][lr][lc],      ga);
    cp16(&As[0][lr + 64][lc], ga + (size_t)64 * K);
    cp16(&Bs[0][lr][lc],      gb);
    if (BNT == 128) cp16(&Bs[0][lr + 64][lc], gb + (size_t)64 * K);
    CP_COMMIT();

    const int ktiles = K / BKH;
    for (int kt = 0; kt < ktiles; kt++) {
        if (kt + 1 < ktiles) {
            int buf = (kt + 1) & 1, k0 = (kt + 1) * BKH;
            cp16(&As[buf][lr][lc],      ga + k0);
            cp16(&As[buf][lr + 64][lc], ga + (size_t)64 * K + k0);
            cp16(&Bs[buf][lr][lc],      gb + k0);
            if (BNT == 128) cp16(&Bs[buf][lr + 64][lc], gb + (size_t)64 * K + k0);
        }
        CP_COMMIT();
        CP_WAIT1();
        __syncthreads();
        const int buf = kt & 1;
#pragma unroll
        for (int kh = 0; kh < 2; kh++) {
            const int koff = kh * 16;
            unsigned a[4][4], bb[NG2][4];
            const int arow = wm + (lane & 15);
            const int akoff = koff + ((lane >> 4) << 3);
#pragma unroll
            for (int mi = 0; mi < 4; mi++) {
                unsigned ad = su32(&As[buf][arow + mi * 16][akoff]);
                LDSM4(a[mi][0], a[mi][1], a[mi][2], a[mi][3], ad);
            }
            const int brow = wn + ((lane & 16) >> 1) + (lane & 7);
            const int bkoff = koff + (lane & 8);
#pragma unroll
            for (int g2 = 0; g2 < NG2; g2++) {
                unsigned ad = su32(&Bs[buf][brow + g2 * 16][bkoff]);
                LDSM4(bb[g2][0], bb[g2][1], bb[g2][2], bb[g2][3], ad);
            }
#pragma unroll
            for (int mi = 0; mi < 4; mi++)
#pragma unroll
                for (int nj = 0; nj < NJ; nj++) {
                    unsigned b0 = bb[nj >> 1][(nj & 1) * 2];
                    unsigned b1 = bb[nj >> 1][(nj & 1) * 2 + 1];
                    MMA16816F(c[mi][nj], a[mi], b0, b1);
                }
        }
        __syncthreads();
    }

    // epilogue
    const int crow = lane >> 2, ccol = (lane & 3) * 2;
#pragma unroll
    for (int mi = 0; mi < 4; mi++) {
#pragma unroll
        for (int half = 0; half < 2; half++) {
            const int m = m0 + wm + mi * 16 + crow + half * 8;
            float s = (MODE == 3) ? rs[(size_t)m * rs_stride] : 0.f;
#pragma unroll
            for (int nj = 0; nj < NJ; nj++) {
                const int n = n0 + wn + nj * 8 + ccol;
                float v0 = c[mi][nj][half * 2 + 0];
                float v1 = c[mi][nj][half * 2 + 1];
                float* p = C + (size_t)m * N + n;
                if (MODE == 0)      { p[0] = v0;                    p[1] = v1; }
                else if (MODE == 1) { p[0] = fmaxf(p[0] + v0, 0.f); p[1] = fmaxf(p[1] + v1, 0.f); }
                else if (MODE == 2) { p[0] += v0;                   p[1] += v1; }
                else                { p[0] += s * v0;               p[1] += s * v1; }
            }
        }
    }
}

// ---------------- split fp32 -> (hi, lo) fp16, flat, vectorized ----------------
__global__ void split2h_kernel(const float* __restrict__ in,
                               __half* __restrict__ hi, __half* __restrict__ lo,
                               int n8) {
    int i = blockIdx.x * 256 + threadIdx.x;
    if (i >= n8) return;
    const float4* p = (const float4*)in + (size_t)i * 2;
    float4 x0 = p[0], x1 = p[1];
    float v[8] = {x0.x, x0.y, x0.z, x0.w, x1.x, x1.y, x1.z, x1.w};
    __align__(16) __half hh[8], ll[8];
#pragma unroll
    for (int k = 0; k < 8; k++) {
        __half h = __float2half_rn(v[k]);
        hh[k] = h;
        ll[k] = __float2half_rn(v[k] - __half2float(h));
    }
    *(uint4*)(hi + (size_t)i * 8) = *(uint4*)hh;
    *(uint4*)(lo + (size_t)i * 8) = *(uint4*)ll;
}

// ---------------- embedding ----------------
__global__ void embed_kernel(const int* __restrict__ tokens,
                             const float* __restrict__ wte,
                             const float* __restrict__ wpe,
                             float* __restrict__ x) {
    int r = blockIdx.x;
    int t = r & (T_ - 1);
    int tok = tokens[r];
    const float* we = wte + (size_t)tok * D_;
    const float* pe = wpe + (size_t)t * D_;
    float* xr = x + (size_t)r * D_;
    for (int i = threadIdx.x; i < D_; i += 256) xr[i] = we[i] + pe[i];
}

// ---------------- layernorm ----------------
__global__ void ln_kernel(const float* __restrict__ in,
                          const float* __restrict__ g,
                          const float* __restrict__ b,
                          float* __restrict__ out) {
    int r = blockIdx.x, tid = threadIdx.x;
    const float* xr = in + (size_t)r * D_;
    float v[3], s = 0.f, ss = 0.f;
#pragma unroll
    for (int n = 0; n < 3; n++) {
        float t = xr[tid + n * 256];
        v[n] = t; s += t; ss += t * t;
    }
    __shared__ float r1[256], r2[256];
    r1[tid] = s; r2[tid] = ss;
    __syncthreads();
    for (int o = 128; o > 0; o >>= 1) {
        if (tid < o) { r1[tid] += r1[tid + o]; r2[tid] += r2[tid + o]; }
        __syncthreads();
    }
    float mu = r1[0] * (1.f / D_);
    float var = r2[0] * (1.f / D_) - mu * mu;
    float rstd = rsqrtf(var + 1e-5f);
    float* orow = out + (size_t)r * D_;
#pragma unroll
    for (int n = 0; n < 3; n++) {
        int i = tid + n * 256;
        orow[i] = (v[n] - mu) * rstd * g[i] + b[i];
    }
}

// ---------------- attention: S = Q K^T * scale (causal tiles only) ----------------
__global__ void __launch_bounds__(256) attn_scores(const float* __restrict__ qkv,
                                                   float* __restrict__ sc) {
    int kt = blockIdx.x, qt = blockIdx.y, bh = blockIdx.z;
    if (kt > qt) return;
    int b = bh / H_, h = bh - b * H_;
    const float* Qb = qkv + (size_t)b * T_ * TD3_ + h * HEAD_;
    const float* Kb = Qb + D_;
    __shared__ float As[16][65], Bs[16][65];
    int tid = threadIdx.x;
    int m = tid >> 2, k4 = (tid & 3) * 4;
    int ty = tid >> 4, tx = tid & 15;
    float acc[4][4] = {};
    for (int k0 = 0; k0 < HEAD_; k0 += 16) {
        float4 a   = *(const float4*)(Qb + (size_t)(qt * 64 + m) * TD3_ + k0 + k4);
        float4 bbv = *(const float4*)(Kb + (size_t)(kt * 64 + m) * TD3_ + k0 + k4);
        __syncthreads();
        As[k4 + 0][m] = a.x;   As[k4 + 1][m] = a.y;   As[k4 + 2][m] = a.z;   As[k4 + 3][m] = a.w;
        Bs[k4 + 0][m] = bbv.x; Bs[k4 + 1][m] = bbv.y; Bs[k4 + 2][m] = bbv.z; Bs[k4 + 3][m] = bbv.w;
        __syncthreads();
#pragma unroll
        for (int k = 0; k < 16; k++) {
            float av[4], bv[4];
#pragma unroll
            for (int i = 0; i < 4; i++) av[i] = As[k][ty * 4 + i];
#pragma unroll
            for (int j = 0; j < 4; j++) bv[j] = Bs[k][tx * 4 + j];
#pragma unroll
            for (int i = 0; i < 4; i++)
#pragma unroll
                for (int j = 0; j < 4; j++) acc[i][j] += av[i] * bv[j];
        }
    }
    float* out = sc + ((size_t)bh << 20);
#pragma unroll
    for (int i = 0; i < 4; i++) {
        int q = qt * 64 + ty * 4 + i;
#pragma unroll
        for (int j = 0; j < 4; j++) {
            int kk = kt * 64 + tx * 4 + j;
            float v = acc[i][j] * 0.125f;
            if (kk > q) v = -1e30f;
            out[(size_t)q * T_ + kk] = v;
        }
    }
}

// ---------------- row softmax over [0, kend) ----------------
__global__ void softmax_rows(float* __restrict__ sc) {
    int q = blockIdx.x, bh = blockIdx.y, tid = threadIdx.x;
    float* row = sc + ((size_t)bh << 20) + (size_t)q * T_;
    int kend = ((q >> 6) + 1) << 6;
    float lmax = -3e38f;
    for (int i = tid; i < kend; i += 256) lmax = fmaxf(lmax, row[i]);
    __shared__ float red[256];
    red[tid] = lmax; __syncthreads();
    for (int o = 128; o > 0; o >>= 1) {
        if (tid < o) red[tid] = fmaxf(red[tid], red[tid + o]);
        __syncthreads();
    }
    float m = red[0];
    __syncthreads();
    float v[4]; int n = 0; float lsum = 0.f;
    for (int i = tid; i < kend; i += 256) {
        float e = __expf(row[i] - m);
        v[n++] = e; lsum += e;
    }
    red[tid] = lsum; __syncthreads();
    for (int o = 128; o > 0; o >>= 1) {
        if (tid < o) red[tid] += red[tid + o];
        __syncthreads();
    }
    float inv = 1.f / red[0];
    n = 0;
    for (int i = tid; i < kend; i += 256) row[i] = v[n++] * inv;
}

// ---------------- attention: O = P V ----------------
__global__ void __launch_bounds__(256) attn_out(const float* __restrict__ sc,
                                                const float* __restrict__ qkv,
                                                float* __restrict__ ao) {
    int qt = blockIdx.x, bh = blockIdx.y;
    int b = bh / H_, h = bh - b * H_;
    const float* P = sc + ((size_t)bh << 20) + (size_t)qt * 64 * T_;
    const float* V = qkv + (size_t)b * T_ * TD3_ + 2 * D_ + h * HEAD_;
    __shared__ float Ps[64][20];
    __shared__ float Vs[16][64];
    int tid = threadIdx.x;
    int m = tid >> 2, k4 = (tid & 3) * 4;
    int kv = tid >> 4, j4 = (tid & 15) * 4;
    int ty = tid >> 4, tx = tid & 15;
    float acc[4][4] = {};
    int kmax = (qt + 1) * 64;
    for (int k0 = 0; k0 < kmax; k0 += 16) {
        float4 p  = *(const float4*)(P + (size_t)m * T_ + k0 + k4);
        float4 vv = *(const float4*)(V + (size_t)(k0 + kv) * TD3_ + j4);
        __syncthreads();
        *(float4*)&Ps[m][k4] = p;
        *(float4*)&Vs[kv][j4] = vv;
        __syncthreads();
#pragma unroll
        for (int k = 0; k < 16; k++) {
            float pv[4], vb[4];
#pragma unroll
            for (int i = 0; i < 4; i++) pv[i] = Ps[ty * 4 + i][k];
            *(float4*)vb = *(const float4*)&Vs[k][tx * 4];
#pragma unroll
            for (int i = 0; i < 4; i++)
#pragma unroll
                for (int j = 0; j < 4; j++) acc[i][j] += pv[i] * vb[j];
        }
    }
    float* O = ao + (size_t)(b * T_ + qt * 64) * D_ + h * HEAD_;
#pragma unroll
    for (int i = 0; i < 4; i++)
#pragma unroll
        for (int j = 0; j < 4; j++)
            O[(size_t)(ty * 4 + i) * D_ + tx * 4 + j] = acc[i][j];
}

// ---------------- router ----------------
__global__ void router_kernel(const float* __restrict__ h,
                              const float* __restrict__ rw,
                              float* __restrict__ w) {
    int r = blockIdx.x;
    int warp = threadIdx.x >> 5, lane = threadIdx.x & 31;
    const float* hr = h + (size_t)r * D_;
    const float* we = rw + (size_t)warp * D_;
    float dot = 0.f;
    for (int i = lane; i < D_; i += 32) dot += hr[i] * we[i];
    for (int o = 16; o > 0; o >>= 1) dot += __shfl_xor_sync(0xffffffffu, dot, o);
    __shared__ float s[E_];
    if (lane == 0) s[warp] = dot;
    __syncthreads();
    if (threadIdx.x == 0) {
        float mx = s[0];
        for (int e = 1; e < E_; e++) mx = fmaxf(mx, s[e]);
        float p[E_], sum = 0.f;
        for (int e = 0; e < E_; e++) { p[e] = __expf(s[e] - mx); sum += p[e]; }
        float inv = 1.f / sum;
        for (int e = 0; e < E_; e++) p[e] *= inv;
        int i1 = 0;
        for (int e = 1; e < E_; e++) if (s[e] > s[i1]) i1 = e;
        int i2 = (i1 == 0) ? 1 : 0;
        for (int e = 0; e < E_; e++) if (e != i1 && s[e] > s[i2]) i2 = e;
        float denom = p[i1] + p[i2] + 1e-8f;
        for (int e = 0; e < E_; e++)
            w[(size_t)r * E_ + e] = (e == i1 || e == i2) ? p[e] / denom : 0.f;
    }
}

// ---------------- host helpers ----------------
static inline void split2h(const float* in, __half* hi, __half* lo, size_t n) {
    unsigned n8 = (unsigned)(n / 8);
    split2h_kernel<<<(n8 + 255) / 256, 256>>>(in, hi, lo, (int)n8);
}

extern "C" void kernel_launch(void* const* d_in, const int* in_sizes, int n_in,
                              void* d_out, int out_size) {
    (void)in_sizes; (void)n_in; (void)out_size;
    const int*   tokens   = (const int*)  d_in[0];
    const float* wte      = (const float*)d_in[1];
    const float* wpe      = (const float*)d_in[2];
    const float* norm0_g  = (const float*)d_in[3];
    const float* norm0_b  = (const float*)d_in[4];
    const float* norm1_g  = (const float*)d_in[5];
    const float* norm1_b  = (const float*)d_in[6];
    const float* norm2_g  = (const float*)d_in[7];
    const float* norm2_b  = (const float*)d_in[8];
    const float* qkv_w    = (const float*)d_in[9];
    const float* proj_w   = (const float*)d_in[10];
    const float* router_w = (const float*)d_in[11];
    const float* fc1      = (const float*)d_in[12];
    const float* fc2      = (const float*)d_in[13];
    const float* lm_head  = (const float*)d_in[14];
    float* out = (float*)d_out;

    float *x, *h, *qkv, *sc, *ao, *w, *hid;
    __half *ahi, *alo, *bhi, *blo, *chi, *clo;
    cudaGetSymbolAddress((void**)&x,   g_x);
    cudaGetSymbolAddress((void**)&h,   g_h);
    cudaGetSymbolAddress((void**)&qkv, g_qkv);
    cudaGetSymbolAddress((void**)&sc,  g_sc);
    cudaGetSymbolAddress((void**)&ao,  g_ao);
    cudaGetSymbolAddress((void**)&w,   g_w);
    cudaGetSymbolAddress((void**)&hid, g_hid);
    cudaGetSymbolAddress((void**)&ahi, g_ahi);
    cudaGetSymbolAddress((void**)&alo, g_alo);
    cudaGetSymbolAddress((void**)&bhi, g_bhi);
    cudaGetSymbolAddress((void**)&blo, g_blo);
    cudaGetSymbolAddress((void**)&chi, g_chi);
    cudaGetSymbolAddress((void**)&clo, g_clo);

    embed_kernel<<<BT_, 256>>>(tokens, wte, wpe, x);
    ln_kernel<<<BT_, 256>>>(x, norm0_g, norm0_b, x);

    for (int l = 0; l < L_; l++) {
        // --- attention ---
        ln_kernel<<<BT_, 256>>>(x, norm1_g + l * D_, norm1_b + l * D_, h);
        split2h(h, ahi, alo, (size_t)BT_ * D_);
        split2h(qkv_w + (size_t)l * TD3_ * D_, bhi, blo, (size_t)TD3_ * D_);
        {
            dim3 g(BT_ / 128, TD3_ / 128);
            gemm_f16<0, 128><<<g, 256>>>(ahi, bhi, qkv, BT_, TD3_, D_, nullptr, 0);
            gemm_f16<2, 128><<<g, 256>>>(alo, bhi, qkv, BT_, TD3_, D_, nullptr, 0);
            gemm_f16<2, 128><<<g, 256>>>(ahi, blo, qkv, BT_, TD3_, D_, nullptr, 0);
        }
        {
            dim3 g(T_ / 64, T_ / 64, B_ * H_);
            attn_scores<<<g, 256>>>(qkv, sc);
        }
        {
            dim3 g(T_, B_ * H_);
            softmax_rows<<<g, 256>>>(sc);
        }
        {
            dim3 g(T_ / 64, B_ * H_);
            attn_out<<<g, 256>>>(sc, qkv, ao);
        }
        split2h(ao, ahi, alo, (size_t)BT_ * D_);
        split2h(proj_w + (size_t)l * D_ * D_, bhi, blo, (size_t)D_ * D_);
        {
            dim3 g(BT_ / 128, D_ / 64);
            gemm_f16<2, 64><<<g, 256>>>(ahi, bhi, x, BT_, D_, D_, nullptr, 0);
            gemm_f16<2, 64><<<g, 256>>>(alo, bhi, x, BT_, D_, D_, nullptr, 0);
            gemm_f16<2, 64><<<g, 256>>>(ahi, blo, x, BT_, D_, D_, nullptr, 0);
        }
        // --- MoE ---
        ln_kernel<<<BT_, 256>>>(x, norm2_g + l * D_, norm2_b + l * D_, h);
        router_kernel<<<BT_, 256>>>(h, router_w + (size_t)l * E_ * D_, w);
        split2h(h, ahi, alo, (size_t)BT_ * D_);
        for (int e = 0; e < E_; e++) {
            split2h(fc1 + ((size_t)(l * E_ + e)) * DFF_ * D_, bhi, blo, (size_t)DFF_ * D_);
            {
                dim3 g(BT_ / 128, DFF_ / 128);
                gemm_f16<0, 128><<<g, 256>>>(ahi, bhi, hid, BT_, DFF_, D_, nullptr, 0);
                gemm_f16<2, 128><<<g, 256>>>(alo, bhi, hid, BT_, DFF_, D_, nullptr, 0);
                gemm_f16<1, 128><<<g, 256>>>(ahi, blo, hid, BT_, DFF_, D_, nullptr, 0); // relu last
            }
            split2h(hid, chi, clo, (size_t)BT_ * DFF_);
            split2h(fc2 + ((size_t)(l * E_ + e)) * D_ * DFF_, bhi, blo, (size_t)D_ * DFF_);
            {
                dim3 g(BT_ / 128, D_ / 64);
                gemm_f16<3, 64><<<g, 256>>>(chi, bhi, x, BT_, D_, DFF_, w + e, E_);
                gemm_f16<3, 64><<<g, 256>>>(clo, bhi, x, BT_, D_, DFF_, w + e, E_);
                gemm_f16<3, 64><<<g, 256>>>(chi, blo, x, BT_, D_, DFF_, w + e, E_);
            }
        }
    }
    split2h(x, ahi, alo, (size_t)BT_ * D_);
    split2h(lm_head, bhi, blo, (size_t)V_ * D_);
    {
        dim3 g(BT_ / 128, V_ / 128);
        gemm_f16<0, 128><<<g, 256>>>(ahi, bhi, out, BT_, V_, D_, nullptr, 0);
        gemm_f16<2, 128><<<g, 256>>>(alo, bhi, out, BT_, V_, D_, nullptr, 0);
        gemm_f16<2, 128><<<g, 256>>>(ahi, blo, out, BT_, V_, D_, nullptr, 0);
    }
}

// round 15
// speedup vs baseline: 2.7409x; 1.3134x over previous
#include <cuda_runtime.h>
#include <cuda_fp16.h>
#include <math.h>
#include <stdint.h>

#define B_   2
#define T_   1024
#define D_   768
#define H_   12
#define L_   4
#define E_   8
#define DFF_ 3072
#define V_   32000
#define HEAD_ 64
#define BT_  (B_ * T_)      // 2048
#define TD3_ (3 * D_)       // 2304

// ---------------- scratch (device globals; no allocation) ----------------
__device__ float g_x  [BT_ * D_];
__device__ float g_h  [BT_ * D_];
__device__ float g_qkv[BT_ * TD3_];
__device__ float g_sc [(size_t)B_ * H_ * T_ * T_];
__device__ float g_ao [BT_ * D_];
__device__ float g_w  [BT_ * E_];
__device__ float g_hid[(size_t)E_ * BT_ * DFF_];   // per-expert fc1 partials
__device__ float g_eo [(size_t)E_ * BT_ * D_];     // per-expert fc2 outputs
__device__ __half g_ahi[BT_ * D_];
__device__ __half g_alo[BT_ * D_];
__device__ __half g_bhi[(size_t)V_ * D_];
__device__ __half g_blo[(size_t)V_ * D_];
__device__ __half g_chi[(size_t)E_ * BT_ * DFF_];
__device__ __half g_clo[(size_t)E_ * BT_ * DFF_];

__device__ __forceinline__ unsigned su32(const void* p) {
    return (unsigned)__cvta_generic_to_shared(p);
}
__device__ __forceinline__ void cp16(void* s, const void* g) {
    asm volatile("cp.async.cg.shared.global [%0], [%1], 16;\n" :: "r"(su32(s)), "l"(g));
}
#define CP_COMMIT() asm volatile("cp.async.commit_group;\n" ::: "memory")
#define CP_WAIT1()  asm volatile("cp.async.wait_group 1;\n" ::: "memory")
#define LDSM4(r0,r1,r2,r3,addr) \
    asm volatile("ldmatrix.sync.aligned.m8n8.x4.shared.b16 {%0,%1,%2,%3}, [%4];" \
                 : "=r"(r0),"=r"(r1),"=r"(r2),"=r"(r3) : "r"(addr))
#define MMA16816F(c,a,b0,b1) \
    asm volatile("mma.sync.aligned.m16n8k16.row.col.f32.f16.f16.f32 " \
                 "{%0,%1,%2,%3},{%4,%5,%6,%7},{%8,%9},{%0,%1,%2,%3};" \
                 : "+f"(c[0]),"+f"(c[1]),"+f"(c[2]),"+f"(c[3]) \
                 : "r"(a[0]),"r"(a[1]),"r"(a[2]),"r"(a[3]),"r"(b0),"r"(b1))

// ---------------- fp16 HMMA NT GEMM (one term per launch; optional z-batch) ----------------
// C[M,N] = A[M,K] * B[N,K]^T   (fp16 split halves; fp32 accumulate)
// MODE 0: C = acc   2: C += acc   5: r = relu(C + acc), split-store r -> (Chi, Clo)
#define BKH 32
#define PADH 8

template <int MODE, int BNT>
__global__ void __launch_bounds__(256) gemm_f16(
    const __half* __restrict__ A, const __half* __restrict__ B,
    float* __restrict__ C, __half* __restrict__ Chi, __half* __restrict__ Clo,
    int M, int N, int K, size_t az, size_t bz, size_t cz) {
    constexpr int WN  = BNT / 4;        // 32 or 16
    constexpr int NJ  = WN / 8;         // 4 or 2
    constexpr int NG2 = WN / 16;        // 2 or 1
    A += (size_t)blockIdx.z * az;
    B += (size_t)blockIdx.z * bz;
    C += (size_t)blockIdx.z * cz;
    if (MODE == 5) { Chi += (size_t)blockIdx.z * cz; Clo += (size_t)blockIdx.z * cz; }
    __shared__ __align__(16) __half As[2][128][BKH + PADH];
    __shared__ __align__(16) __half Bs[2][BNT][BKH + PADH];
    const int tid = threadIdx.x;
    const int lane = tid & 31, warp = tid >> 5;
    const int wm = (warp >> 2) * 64;
    const int wn = (warp & 3) * WN;
    const int m0 = blockIdx.x * 128, n0 = blockIdx.y * BNT;

    const int lr = tid >> 2, lc = (tid & 3) * 8;
    const __half* ga = A + (size_t)(m0 + lr) * K + lc;
    const __half* gb = B + (size_t)(n0 + lr) * K + lc;

    float c[4][NJ][4];
#pragma unroll
    for (int i = 0; i < 4; i++)
#pragma unroll
        for (int j = 0; j < NJ; j++)
#pragma unroll
            for (int q = 0; q < 4; q++) c[i][j][q] = 0.f;

    cp16(&As[0][lr][lc],      ga);
    cp16(&As[0][lr + 64][lc], ga + (size_t)64 * K);
    cp16(&Bs[0][lr][lc],      gb);
    if (BNT == 128) cp16(&Bs[0][lr + 64][lc], gb + (size_t)64 * K);
    CP_COMMIT();

    const int ktiles = K / BKH;
    for (int kt = 0; kt < ktiles; kt++) {
        if (kt + 1 < ktiles) {
            int buf = (kt + 1) & 1, k0 = (kt + 1) * BKH;
            cp16(&As[buf][lr][lc],      ga + k0);
            cp16(&As[buf][lr + 64][lc], ga + (size_t)64 * K + k0);
            cp16(&Bs[buf][lr][lc],      gb + k0);
            if (BNT == 128) cp16(&Bs[buf][lr + 64][lc], gb + (size_t)64 * K + k0);
        }
        CP_COMMIT();
        CP_WAIT1();
        __syncthreads();
        const int buf = kt & 1;
#pragma unroll
        for (int kh = 0; kh < 2; kh++) {
            const int koff = kh * 16;
            unsigned a[4][4], bb[NG2][4];
            const int arow = wm + (lane & 15);
            const int akoff = koff + ((lane >> 4) << 3);
#pragma unroll
            for (int mi = 0; mi < 4; mi++) {
                unsigned ad = su32(&As[buf][arow + mi * 16][akoff]);
                LDSM4(a[mi][0], a[mi][1], a[mi][2], a[mi][3], ad);
            }
            const int brow = wn + ((lane & 16) >> 1) + (lane & 7);
            const int bkoff = koff + (lane & 8);
#pragma unroll
            for (int g2 = 0; g2 < NG2; g2++) {
                unsigned ad = su32(&Bs[buf][brow + g2 * 16][bkoff]);
                LDSM4(bb[g2][0], bb[g2][1], bb[g2][2], bb[g2][3], ad);
            }
#pragma unroll
            for (int mi = 0; mi < 4; mi++)
#pragma unroll
                for (int nj = 0; nj < NJ; nj++) {
                    unsigned b0 = bb[nj >> 1][(nj & 1) * 2];
                    unsigned b1 = bb[nj >> 1][(nj & 1) * 2 + 1];
                    MMA16816F(c[mi][nj], a[mi], b0, b1);
                }
        }
        __syncthreads();
    }

    const int crow = lane >> 2, ccol = (lane & 3) * 2;
#pragma unroll
    for (int mi = 0; mi < 4; mi++) {
#pragma unroll
        for (int half = 0; half < 2; half++) {
            const int m = m0 + wm + mi * 16 + crow + half * 8;
#pragma unroll
            for (int nj = 0; nj < NJ; nj++) {
                const int n = n0 + wn + nj * 8 + ccol;
                float v0 = c[mi][nj][half * 2 + 0];
                float v1 = c[mi][nj][half * 2 + 1];
                float* p = C + (size_t)m * N + n;
                if (MODE == 0)      { p[0] = v0;  p[1] = v1; }
                else if (MODE == 2) { p[0] += v0; p[1] += v1; }
                else {  // MODE 5: relu(C+acc) -> split fp16 (values identical to split2h(relu))
                    float r0 = fmaxf(p[0] + v0, 0.f);
                    float r1 = fmaxf(p[1] + v1, 0.f);
                    __half h0 = __float2half_rn(r0), h1 = __float2half_rn(r1);
                    Chi[(size_t)m * N + n]     = h0;
                    Chi[(size_t)m * N + n + 1] = h1;
                    Clo[(size_t)m * N + n]     = __float2half_rn(r0 - __half2float(h0));
                    Clo[(size_t)m * N + n + 1] = __float2half_rn(r1 - __half2float(h1));
                }
            }
        }
    }
}

// ---------------- split fp32 -> (hi, lo) fp16, flat, vectorized ----------------
__global__ void split2h_kernel(const float* __restrict__ in,
                               __half* __restrict__ hi, __half* __restrict__ lo,
                               int n8) {
    int i = blockIdx.x * 256 + threadIdx.x;
    if (i >= n8) return;
    const float4* p = (const float4*)in + (size_t)i * 2;
    float4 x0 = p[0], x1 = p[1];
    float v[8] = {x0.x, x0.y, x0.z, x0.w, x1.x, x1.y, x1.z, x1.w};
    __align__(16) __half hh[8], ll[8];
#pragma unroll
    for (int k = 0; k < 8; k++) {
        __half h = __float2half_rn(v[k]);
        hh[k] = h;
        ll[k] = __float2half_rn(v[k] - __half2float(h));
    }
    *(uint4*)(hi + (size_t)i * 8) = *(uint4*)hh;
    *(uint4*)(lo + (size_t)i * 8) = *(uint4*)ll;
}

// ---------------- MoE reduce: x += sum_e w[r][e] * eo[e][r][:] ----------------
__global__ void moe_reduce(const float* __restrict__ eo,
                           const float* __restrict__ w,
                           float* __restrict__ x) {
    int r = blockIdx.x, tid = threadIdx.x;
    __shared__ float ws[E_];
    if (tid < E_) ws[tid] = w[(size_t)r * E_ + tid];
    __syncthreads();
    for (int d = tid; d < D_; d += 256) {
        float acc = x[(size_t)r * D_ + d];
#pragma unroll
        for (int e = 0; e < E_; e++)
            acc += ws[e] * eo[((size_t)e * BT_ + r) * D_ + d];
        x[(size_t)r * D_ + d] = acc;
    }
}

// ---------------- embedding ----------------
__global__ void embed_kernel(const int* __restrict__ tokens,
                             const float* __restrict__ wte,
                             const float* __restrict__ wpe,
                             float* __restrict__ x) {
    int r = blockIdx.x;
    int t = r & (T_ - 1);
    int tok = tokens[r];
    const float* we = wte + (size_t)tok * D_;
    const float* pe = wpe + (size_t)t * D_;
    float* xr = x + (size_t)r * D_;
    for (int i = threadIdx.x; i < D_; i += 256) xr[i] = we[i] + pe[i];
}

// ---------------- layernorm ----------------
__global__ void ln_kernel(const float* __restrict__ in,
                          const float* __restrict__ g,
                          const float* __restrict__ b,
                          float* __restrict__ out) {
    int r = blockIdx.x, tid = threadIdx.x;
    const float* xr = in + (size_t)r * D_;
    float v[3], s = 0.f, ss = 0.f;
#pragma unroll
    for (int n = 0; n < 3; n++) {
        float t = xr[tid + n * 256];
        v[n] = t; s += t; ss += t * t;
    }
    __shared__ float r1[256], r2[256];
    r1[tid] = s; r2[tid] = ss;
    __syncthreads();
    for (int o = 128; o > 0; o >>= 1) {
        if (tid < o) { r1[tid] += r1[tid + o]; r2[tid] += r2[tid + o]; }
        __syncthreads();
    }
    float mu = r1[0] * (1.f / D_);
    float var = r2[0] * (1.f / D_) - mu * mu;
    float rstd = rsqrtf(var + 1e-5f);
    float* orow = out + (size_t)r * D_;
#pragma unroll
    for (int n = 0; n < 3; n++) {
        int i = tid + n * 256;
        orow[i] = (v[n] - mu) * rstd * g[i] + b[i];
    }
}

// ---------------- attention: S = Q K^T * scale (causal tiles only) ----------------
__global__ void __launch_bounds__(256) attn_scores(const float* __restrict__ qkv,
                                                   float* __restrict__ sc) {
    int kt = blockIdx.x, qt = blockIdx.y, bh = blockIdx.z;
    if (kt > qt) return;
    int b = bh / H_, h = bh - b * H_;
    const float* Qb = qkv + (size_t)b * T_ * TD3_ + h * HEAD_;
    const float* Kb = Qb + D_;
    __shared__ float As[16][65], Bs[16][65];
    int tid = threadIdx.x;
    int m = tid >> 2, k4 = (tid & 3) * 4;
    int ty = tid >> 4, tx = tid & 15;
    float acc[4][4] = {};
    for (int k0 = 0; k0 < HEAD_; k0 += 16) {
        float4 a   = *(const float4*)(Qb + (size_t)(qt * 64 + m) * TD3_ + k0 + k4);
        float4 bbv = *(const float4*)(Kb + (size_t)(kt * 64 + m) * TD3_ + k0 + k4);
        __syncthreads();
        As[k4 + 0][m] = a.x;   As[k4 + 1][m] = a.y;   As[k4 + 2][m] = a.z;   As[k4 + 3][m] = a.w;
        Bs[k4 + 0][m] = bbv.x; Bs[k4 + 1][m] = bbv.y; Bs[k4 + 2][m] = bbv.z; Bs[k4 + 3][m] = bbv.w;
        __syncthreads();
#pragma unroll
        for (int k = 0; k < 16; k++) {
            float av[4], bv[4];
#pragma unroll
            for (int i = 0; i < 4; i++) av[i] = As[k][ty * 4 + i];
#pragma unroll
            for (int j = 0; j < 4; j++) bv[j] = Bs[k][tx * 4 + j];
#pragma unroll
            for (int i = 0; i < 4; i++)
#pragma unroll
                for (int j = 0; j < 4; j++) acc[i][j] += av[i] * bv[j];
        }
    }
    float* out = sc + ((size_t)bh << 20);
#pragma unroll
    for (int i = 0; i < 4; i++) {
        int q = qt * 64 + ty * 4 + i;
#pragma unroll
        for (int j = 0; j < 4; j++) {
            int kk = kt * 64 + tx * 4 + j;
            float v = acc[i][j] * 0.125f;
            if (kk > q) v = -1e30f;
            out[(size_t)q * T_ + kk] = v;
        }
    }
}

// ---------------- row softmax over [0, kend) ----------------
__global__ void softmax_rows(float* __restrict__ sc) {
    int q = blockIdx.x, bh = blockIdx.y, tid = threadIdx.x;
    float* row = sc + ((size_t)bh << 20) + (size_t)q * T_;
    int kend = ((q >> 6) + 1) << 6;
    float lmax = -3e38f;
    for (int i = tid; i < kend; i += 256) lmax = fmaxf(lmax, row[i]);
    __shared__ float red[256];
    red[tid] = lmax; __syncthreads();
    for (int o = 128; o > 0; o >>= 1) {
        if (tid < o) red[tid] = fmaxf(red[tid], red[tid + o]);
        __syncthreads();
    }
    float m = red[0];
    __syncthreads();
    float v[4]; int n = 0; float lsum = 0.f;
    for (int i = tid; i < kend; i += 256) {
        float e = __expf(row[i] - m);
        v[n++] = e; lsum += e;
    }
    red[tid] = lsum; __syncthreads();
    for (int o = 128; o > 0; o >>= 1) {
        if (tid < o) red[tid] += red[tid + o];
        __syncthreads();
    }
    float inv = 1.f / red[0];
    n = 0;
    for (int i = tid; i < kend; i += 256) row[i] = v[n++] * inv;
}

// ---------------- attention: O = P V ----------------
__global__ void __launch_bounds__(256) attn_out(const float* __restrict__ sc,
                                                const float* __restrict__ qkv,
                                                float* __restrict__ ao) {
    int qt = blockIdx.x, bh = blockIdx.y;
    int b = bh / H_, h = bh - b * H_;
    const float* P = sc + ((size_t)bh << 20) + (size_t)qt * 64 * T_;
    const float* V = qkv + (size_t)b * T_ * TD3_ + 2 * D_ + h * HEAD_;
    __shared__ float Ps[64][20];
    __shared__ float Vs[16][64];
    int tid = threadIdx.x;
    int m = tid >> 2, k4 = (tid & 3) * 4;
    int kv = tid >> 4, j4 = (tid & 15) * 4;
    int ty = tid >> 4, tx = tid & 15;
    float acc[4][4] = {};
    int kmax = (qt + 1) * 64;
    for (int k0 = 0; k0 < kmax; k0 += 16) {
        float4 p  = *(const float4*)(P + (size_t)m * T_ + k0 + k4);
        float4 vv = *(const float4*)(V + (size_t)(k0 + kv) * TD3_ + j4);
        __syncthreads();
        *(float4*)&Ps[m][k4] = p;
        *(float4*)&Vs[kv][j4] = vv;
        __syncthreads();
#pragma unroll
        for (int k = 0; k < 16; k++) {
            float pv[4], vb[4];
#pragma unroll
            for (int i = 0; i < 4; i++) pv[i] = Ps[ty * 4 + i][k];
            *(float4*)vb = *(const float4*)&Vs[k][tx * 4];
#pragma unroll
            for (int i = 0; i < 4; i++)
#pragma unroll
                for (int j = 0; j < 4; j++) acc[i][j] += pv[i] * vb[j];
        }
    }
    float* O = ao + (size_t)(b * T_ + qt * 64) * D_ + h * HEAD_;
#pragma unroll
    for (int i = 0; i < 4; i++)
#pragma unroll
        for (int j = 0; j < 4; j++)
            O[(size_t)(ty * 4 + i) * D_ + tx * 4 + j] = acc[i][j];
}

// ---------------- router ----------------
__global__ void router_kernel(const float* __restrict__ h,
                              const float* __restrict__ rw,
                              float* __restrict__ w) {
    int r = blockIdx.x;
    int warp = threadIdx.x >> 5, lane = threadIdx.x & 31;
    const float* hr = h + (size_t)r * D_;
    const float* we = rw + (size_t)warp * D_;
    float dot = 0.f;
    for (int i = lane; i < D_; i += 32) dot += hr[i] * we[i];
    for (int o = 16; o > 0; o >>= 1) dot += __shfl_xor_sync(0xffffffffu, dot, o);
    __shared__ float s[E_];
    if (lane == 0) s[warp] = dot;
    __syncthreads();
    if (threadIdx.x == 0) {
        float mx = s[0];
        for (int e = 1; e < E_; e++) mx = fmaxf(mx, s[e]);
        float p[E_], sum = 0.f;
        for (int e = 0; e < E_; e++) { p[e] = __expf(s[e] - mx); sum += p[e]; }
        float inv = 1.f / sum;
        for (int e = 0; e < E_; e++) p[e] *= inv;
        int i1 = 0;
        for (int e = 1; e < E_; e++) if (s[e] > s[i1]) i1 = e;
        int i2 = (i1 == 0) ? 1 : 0;
        for (int e = 0; e < E_; e++) if (e != i1 && s[e] > s[i2]) i2 = e;
        float denom = p[i1] + p[i2] + 1e-8f;
        for (int e = 0; e < E_; e++)
            w[(size_t)r * E_ + e] = (e == i1 || e == i2) ? p[e] / denom : 0.f;
    }
}

// ---------------- host helpers ----------------
static inline void split2h(const float* in, __half* hi, __half* lo, size_t n) {
    unsigned n8 = (unsigned)(n / 8);
    split2h_kernel<<<(n8 + 255) / 256, 256>>>(in, hi, lo, (int)n8);
}

extern "C" void kernel_launch(void* const* d_in, const int* in_sizes, int n_in,
                              void* d_out, int out_size) {
    (void)in_sizes; (void)n_in; (void)out_size;
    const int*   tokens   = (const int*)  d_in[0];
    const float* wte      = (const float*)d_in[1];
    const float* wpe      = (const float*)d_in[2];
    const float* norm0_g  = (const float*)d_in[3];
    const float* norm0_b  = (const float*)d_in[4];
    const float* norm1_g  = (const float*)d_in[5];
    const float* norm1_b  = (const float*)d_in[6];
    const float* norm2_g  = (const float*)d_in[7];
    const float* norm2_b  = (const float*)d_in[8];
    const float* qkv_w    = (const float*)d_in[9];
    const float* proj_w   = (const float*)d_in[10];
    const float* router_w = (const float*)d_in[11];
    const float* fc1      = (const float*)d_in[12];
    const float* fc2      = (const float*)d_in[13];
    const float* lm_head  = (const float*)d_in[14];
    float* out = (float*)d_out;

    float *x, *h, *qkv, *sc, *ao, *w, *hid, *eo;
    __half *ahi, *alo, *bhi, *blo, *chi, *clo;
    cudaGetSymbolAddress((void**)&x,   g_x);
    cudaGetSymbolAddress((void**)&h,   g_h);
    cudaGetSymbolAddress((void**)&qkv, g_qkv);
    cudaGetSymbolAddress((void**)&sc,  g_sc);
    cudaGetSymbolAddress((void**)&ao,  g_ao);
    cudaGetSymbolAddress((void**)&w,   g_w);
    cudaGetSymbolAddress((void**)&hid, g_hid);
    cudaGetSymbolAddress((void**)&eo,  g_eo);
    cudaGetSymbolAddress((void**)&ahi, g_ahi);
    cudaGetSymbolAddress((void**)&alo, g_alo);
    cudaGetSymbolAddress((void**)&bhi, g_bhi);
    cudaGetSymbolAddress((void**)&blo, g_blo);
    cudaGetSymbolAddress((void**)&chi, g_chi);
    cudaGetSymbolAddress((void**)&clo, g_clo);

    embed_kernel<<<BT_, 256>>>(tokens, wte, wpe, x);
    ln_kernel<<<BT_, 256>>>(x, norm0_g, norm0_b, x);

    const size_t zF1B = (size_t)DFF_ * D_;   // fc1 weight z-stride (elems)
    const size_t zF2B = (size_t)D_ * DFF_;   // fc2 weight z-stride
    const size_t zHID = (size_t)BT_ * DFF_;  // hid / chi / clo z-stride
    const size_t zEO  = (size_t)BT_ * D_;    // eo z-stride

    for (int l = 0; l < L_; l++) {
        // --- attention ---
        ln_kernel<<<BT_, 256>>>(x, norm1_g + l * D_, norm1_b + l * D_, h);
        split2h(h, ahi, alo, (size_t)BT_ * D_);
        split2h(qkv_w + (size_t)l * TD3_ * D_, bhi, blo, (size_t)TD3_ * D_);
        {
            dim3 g(BT_ / 128, TD3_ / 128);
            gemm_f16<0, 128><<<g, 256>>>(ahi, bhi, qkv, 0, 0, BT_, TD3_, D_, 0, 0, 0);
            gemm_f16<2, 128><<<g, 256>>>(alo, bhi, qkv, 0, 0, BT_, TD3_, D_, 0, 0, 0);
            gemm_f16<2, 128><<<g, 256>>>(ahi, blo, qkv, 0, 0, BT_, TD3_, D_, 0, 0, 0);
        }
        {
            dim3 g(T_ / 64, T_ / 64, B_ * H_);
            attn_scores<<<g, 256>>>(qkv, sc);
        }
        {
            dim3 g(T_, B_ * H_);
            softmax_rows<<<g, 256>>>(sc);
        }
        {
            dim3 g(T_ / 64, B_ * H_);
            attn_out<<<g, 256>>>(sc, qkv, ao);
        }
        split2h(ao, ahi, alo, (size_t)BT_ * D_);
        split2h(proj_w + (size_t)l * D_ * D_, bhi, blo, (size_t)D_ * D_);
        {
            dim3 g(BT_ / 128, D_ / 64);
            gemm_f16<2, 64><<<g, 256>>>(ahi, bhi, x, 0, 0, BT_, D_, D_, 0, 0, 0);
            gemm_f16<2, 64><<<g, 256>>>(alo, bhi, x, 0, 0, BT_, D_, D_, 0, 0, 0);
            gemm_f16<2, 64><<<g, 256>>>(ahi, blo, x, 0, 0, BT_, D_, D_, 0, 0, 0);
        }
        // --- MoE (all experts batched over blockIdx.z) ---
        ln_kernel<<<BT_, 256>>>(x, norm2_g + l * D_, norm2_b + l * D_, h);
        router_kernel<<<BT_, 256>>>(h, router_w + (size_t)l * E_ * D_, w);
        split2h(h, ahi, alo, (size_t)BT_ * D_);
        split2h(fc1 + (size_t)l * E_ * DFF_ * D_, bhi, blo, (size_t)E_ * DFF_ * D_);
        {
            dim3 g(BT_ / 128, DFF_ / 128, E_);
            gemm_f16<0, 128><<<g, 256>>>(ahi, bhi, hid, 0, 0, BT_, DFF_, D_, 0, zF1B, zHID);
            gemm_f16<2, 128><<<g, 256>>>(alo, bhi, hid, 0, 0, BT_, DFF_, D_, 0, zF1B, zHID);
            gemm_f16<5, 128><<<g, 256>>>(ahi, blo, hid, chi, clo, BT_, DFF_, D_, 0, zF1B, zHID);
        }
        split2h(fc2 + (size_t)l * E_ * D_ * DFF_, bhi, blo, (size_t)E_ * D_ * DFF_);
        {
            dim3 g(BT_ / 128, D_ / 128, E_);
            gemm_f16<0, 128><<<g, 256>>>(chi, bhi, eo, 0, 0, BT_, D_, DFF_, zHID, zF2B, zEO);
            gemm_f16<2, 128><<<g, 256>>>(clo, bhi, eo, 0, 0, BT_, D_, DFF_, zHID, zF2B, zEO);
            gemm_f16<2, 128><<<g, 256>>>(chi, blo, eo, 0, 0, BT_, D_, DFF_, zHID, zF2B, zEO);
        }
        moe_reduce<<<BT_, 256>>>(eo, w, x);
    }
    split2h(x, ahi, alo, (size_t)BT_ * D_);
    split2h(lm_head, bhi, blo, (size_t)V_ * D_);
    {
        dim3 g(BT_ / 128, V_ / 128);
        gemm_f16<0, 128><<<g, 256>>>(ahi, bhi, out, 0, 0, BT_, V_, D_, 0, 0, 0);
        gemm_f16<2, 128><<<g, 256>>>(alo, bhi, out, 0, 0, BT_, V_, D_, 0, 0, 0);
        gemm_f16<2, 128><<<g, 256>>>(ahi, blo, out, 0, 0, BT_, V_, D_, 0, 0, 0);
    }
}